// round 5
// baseline (speedup 1.0000x reference)
#include <cuda_runtime.h>

#define Hdim 128
#define NNODES 50000
#define NEDGES 800000
#define TILE 64
#define LDA 66       // padded feature-major stride (even => 8B-aligned pairs)
#define KCHUNK 64    // W staging chunk (64 x 128 fp32 = 32KB)

__device__ int   g_is64;
__device__ float g_mi[(long long)NNODES * Hdim];  // segment-summed m_i scratch
__device__ float g_P [(long long)NNODES * Hdim];  // h @ We1[0:128]   + be1
__device__ float g_Q [(long long)NNODES * Hdim];  // h @ We1[128:256]

// ---------- f32x2 helpers ----------
__device__ __forceinline__ unsigned long long pk2(float lo, float hi) {
    unsigned long long r;
    asm("mov.b64 %0, {%1,%2};" : "=l"(r) : "f"(lo), "f"(hi));
    return r;
}
__device__ __forceinline__ void upk2(unsigned long long v, float& lo, float& hi) {
    asm("mov.b64 {%0,%1}, %2;" : "=f"(lo), "=f"(hi) : "l"(v));
}
#define FMA2(d, a, b) asm("fma.rn.f32x2 %0, %1, %2, %0;" : "+l"(d) : "l"(a), "l"(b))

__device__ __forceinline__ void red_add_v4(float* p, float a, float b, float c, float d) {
    asm volatile("red.global.add.v4.f32 [%0], {%1,%2,%3,%4};"
                 :: "l"(p), "f"(a), "f"(b), "f"(c), "f"(d) : "memory");
}

__device__ __forceinline__ float silu_f(float v) { return v / (1.0f + __expf(-v)); }

// ============================================================================
// Warp-per-column-group GEMM for the edge kernel.
// C[64 edges x 128 cols] = A[64 x 128] * W[128 x 128] + bias
// 256 threads / 8 warps. Warp w owns cols [w*16, w*16+16); lane owns edges
// {2*lane, 2*lane+1}. W staged in smem in two 64-k chunks; per k the warp
// reads 16 W floats at a warp-uniform address (LDS broadcast) and each lane
// reads one float2 of A (conflict-free). 16 FFMA2 per k per thread.
// PACKING: acc[e][j] = packed cols (c0+2j, c0+2j+1) of edge e  (e in {e0,e1}).
// ============================================================================
__device__ __forceinline__ void gemm_warpcol(
    const float* __restrict__ As, float* __restrict__ Ws,
    const float* __restrict__ W, const float* __restrict__ bias,
    unsigned long long acc[2][8], int tid, int lane, int c0) {
    {
        ulonglong2 b01 = *(const ulonglong2*)(bias + c0);
        ulonglong2 b23 = *(const ulonglong2*)(bias + c0 + 4);
        ulonglong2 b45 = *(const ulonglong2*)(bias + c0 + 8);
        ulonglong2 b67 = *(const ulonglong2*)(bias + c0 + 12);
        acc[0][0] = acc[1][0] = b01.x;  acc[0][1] = acc[1][1] = b01.y;
        acc[0][2] = acc[1][2] = b23.x;  acc[0][3] = acc[1][3] = b23.y;
        acc[0][4] = acc[1][4] = b45.x;  acc[0][5] = acc[1][5] = b45.y;
        acc[0][6] = acc[1][6] = b67.x;  acc[0][7] = acc[1][7] = b67.y;
    }
#pragma unroll
    for (int chunk = 0; chunk < Hdim / KCHUNK; chunk++) {
        __syncthreads();  // previous Ws consumers / As producers done
        {
            const float4* src = (const float4*)(W + (long long)chunk * KCHUNK * Hdim);
            float4* dst = (float4*)Ws;
#pragma unroll
            for (int i = 0; i < (KCHUNK * Hdim / 4) / 256; i++)
                dst[tid + i * 256] = __ldg(src + tid + i * 256);
        }
        __syncthreads();
        const float* ap = As + chunk * KCHUNK * LDA + 2 * lane;
        const float* wp = Ws + c0;
#pragma unroll 4
        for (int kk = 0; kk < KCHUNK; kk++) {
            ulonglong2 w01 = *(const ulonglong2*)(wp);
            ulonglong2 w23 = *(const ulonglong2*)(wp + 4);
            ulonglong2 w45 = *(const ulonglong2*)(wp + 8);
            ulonglong2 w67 = *(const ulonglong2*)(wp + 12);
            float2 av = *(const float2*)ap;
            unsigned long long a0 = pk2(av.x, av.x);
            unsigned long long a1 = pk2(av.y, av.y);
            FMA2(acc[0][0], w01.x, a0); FMA2(acc[1][0], w01.x, a1);
            FMA2(acc[0][1], w01.y, a0); FMA2(acc[1][1], w01.y, a1);
            FMA2(acc[0][2], w23.x, a0); FMA2(acc[1][2], w23.x, a1);
            FMA2(acc[0][3], w23.y, a0); FMA2(acc[1][3], w23.y, a1);
            FMA2(acc[0][4], w45.x, a0); FMA2(acc[1][4], w45.x, a1);
            FMA2(acc[0][5], w45.y, a0); FMA2(acc[1][5], w45.y, a1);
            FMA2(acc[0][6], w67.x, a0); FMA2(acc[1][6], w67.x, a1);
            FMA2(acc[0][7], w67.y, a0); FMA2(acc[1][7], w67.y, a1);
            wp += Hdim; ap += LDA;
        }
    }
}

// ---------- R1-style GEMM tile (prep/node): 256 thr, 8 rows x 4 cols ----------
template <int K>
__device__ __forceinline__ void gemm_tile(const float* __restrict__ As,
                                          const float* __restrict__ W,
                                          const float* __restrict__ bias,
                                          unsigned long long acc[4][4],
                                          int tx, int r0) {
    float4 b4 = bias ? __ldg((const float4*)(bias + tx * 4))
                     : make_float4(0.f, 0.f, 0.f, 0.f);
#pragma unroll
    for (int i = 0; i < 4; i++) {
        acc[i][0] = pk2(b4.x, b4.x);
        acc[i][1] = pk2(b4.y, b4.y);
        acc[i][2] = pk2(b4.z, b4.z);
        acc[i][3] = pk2(b4.w, b4.w);
    }
#pragma unroll 4
    for (int k = 0; k < K; k++) {
        float4 w = __ldg((const float4*)(W + (long long)k * Hdim + tx * 4));
        unsigned long long w0 = pk2(w.x, w.x);
        unsigned long long w1 = pk2(w.y, w.y);
        unsigned long long w2 = pk2(w.z, w.z);
        unsigned long long w3 = pk2(w.w, w.w);
        const float* ak = As + k * LDA + r0;
#pragma unroll
        for (int i = 0; i < 4; i++) {
            unsigned long long a2 = *(const unsigned long long*)(ak + 2 * i);
            FMA2(acc[i][0], a2, w0);
            FMA2(acc[i][1], a2, w1);
            FMA2(acc[i][2], a2, w2);
            FMA2(acc[i][3], a2, w3);
        }
    }
}

// ---------- index dtype detection (int32 vs int64) ----------
__global__ void detect_kernel(const int* ei32) {
    if (blockIdx.x == 0 && threadIdx.x == 0) {
        int f = 1;
        for (int i = 0; i < 1024; i++) {
            if (ei32[2 * i + 1] != 0) { f = 0; break; }
        }
        g_is64 = f;
    }
}

// ---------- init: zero m_i scratch, seed out_x = x ----------
__global__ void init_kernel(const float* __restrict__ x, float* __restrict__ out_x) {
    long long i = (long long)blockIdx.x * blockDim.x + threadIdx.x;
    if (i < (long long)NNODES * Hdim) g_mi[i] = 0.0f;
    if (i < (long long)NNODES * 3)    out_x[i] = x[i];
}

// ---------- prep: P = h @ We1[0:128] + be1 ; Q = h @ We1[128:256] ----------
__global__ void __launch_bounds__(256) prep_kernel(
    const float* __restrict__ h,
    const float* __restrict__ We1, const float* __restrict__ be1) {
    extern __shared__ float sm[];
    float* As = sm;  // 128 * LDA

    const int tid = threadIdx.x;
    const int tx = tid & 31, ty = tid >> 5;
    const int r0 = ty * 8;
    const int nb = blockIdx.x * TILE;

    for (int e = ty; e < TILE; e += 8) {
        const int node = nb + e;
        const int d0 = tx * 4;
        float4 hv = make_float4(0.f, 0.f, 0.f, 0.f);
        if (node < NNODES) hv = __ldg((const float4*)(h + (long long)node * Hdim + d0));
        As[(d0 + 0) * LDA + e] = hv.x;
        As[(d0 + 1) * LDA + e] = hv.y;
        As[(d0 + 2) * LDA + e] = hv.z;
        As[(d0 + 3) * LDA + e] = hv.w;
    }
    __syncthreads();

    unsigned long long acc[4][4];

    gemm_tile<128>(As, We1, be1, acc, tx, r0);
#pragma unroll
    for (int i = 0; i < 4; i++) {
        const int n0 = nb + r0 + 2 * i, n1 = n0 + 1;
        float4 oA, oB;
        float v0, v1;
        upk2(acc[i][0], v0, v1); oA.x = v0; oB.x = v1;
        upk2(acc[i][1], v0, v1); oA.y = v0; oB.y = v1;
        upk2(acc[i][2], v0, v1); oA.z = v0; oB.z = v1;
        upk2(acc[i][3], v0, v1); oA.w = v0; oB.w = v1;
        if (n0 < NNODES) *(float4*)(g_P + (long long)n0 * Hdim + tx * 4) = oA;
        if (n1 < NNODES) *(float4*)(g_P + (long long)n1 * Hdim + tx * 4) = oB;
    }

    gemm_tile<128>(As, We1 + 128 * Hdim, (const float*)0, acc, tx, r0);
#pragma unroll
    for (int i = 0; i < 4; i++) {
        const int n0 = nb + r0 + 2 * i, n1 = n0 + 1;
        float4 oA, oB;
        float v0, v1;
        upk2(acc[i][0], v0, v1); oA.x = v0; oB.x = v1;
        upk2(acc[i][1], v0, v1); oA.y = v0; oB.y = v1;
        upk2(acc[i][2], v0, v1); oA.z = v0; oB.z = v1;
        upk2(acc[i][3], v0, v1); oA.w = v0; oB.w = v1;
        if (n0 < NNODES) *(float4*)(g_Q + (long long)n0 * Hdim + tx * 4) = oA;
        if (n1 < NNODES) *(float4*)(g_Q + (long long)n1 * Hdim + tx * 4) = oB;
    }
}

// ---------- edge kernel ----------
__global__ void __launch_bounds__(256, 3) edge_kernel(
    const float* __restrict__ x, const void* __restrict__ ei,
    const float* __restrict__ We1,
    const float* __restrict__ We2, const float* __restrict__ be2,
    const float* __restrict__ Wc1, const float* __restrict__ bc1,
    const float* __restrict__ Wc2,
    float* __restrict__ out_x) {
    extern __shared__ float sm[];
    float* As = sm;                       // 128 * LDA (m1, later m_ij)
    float* Ws = As + 128 * LDA;           // KCHUNK * 128 (weight stage)
    float* nd = Ws + KCHUNK * Hdim;       // 3 * TILE
    float* d2s = nd + 3 * TILE;           // TILE
    float* sf  = d2s + TILE;              // TILE (force-scalar partial sums)
    int*  rowi = (int*)(sf + TILE);       // TILE
    int*  coli = rowi + TILE;             // TILE

    const int tid = threadIdx.x;
    const int wid = tid >> 5, lane = tid & 31;
    const int c0 = wid * 16;              // this warp's 16 columns
    const int e0 = lane * 2, e1 = e0 + 1; // this lane's 2 edges
    const int eb = blockIdx.x * TILE;
    const int is64 = g_is64;

    // 1) indices + coord geometry (+ zero force accumulators)
    if (tid < TILE) {
        int e = tid;
        long long r, c;
        if (is64) {
            const long long* p = (const long long*)ei;
            r = p[eb + e]; c = p[NEDGES + eb + e];
        } else {
            const int* p = (const int*)ei;
            r = p[eb + e]; c = p[NEDGES + eb + e];
        }
        rowi[e] = (int)r; coli[e] = (int)c;
        sf[e] = 0.0f;
        float dx = __ldg(x + r * 3 + 0) - __ldg(x + c * 3 + 0);
        float dy = __ldg(x + r * 3 + 1) - __ldg(x + c * 3 + 1);
        float dz = __ldg(x + r * 3 + 2) - __ldg(x + c * 3 + 2);
        float d2 = dx * dx + dy * dy + dz * dz;
        float dist = sqrtf(d2);
        d2s[e] = d2;
        float inv = 1.0f / (dist + 1e-8f);
        nd[0 * TILE + e] = dx * inv;
        nd[1 * TILE + e] = dy * inv;
        nd[2 * TILE + e] = dz * inv;
    }
    __syncthreads();

    // 2) m1 = silu(P[row] + Q[col] + d2 * We1[256])  (feature-major into As)
    {
        const int d0 = lane * 4;
        float4 w1c = __ldg((const float4*)(We1 + 256 * Hdim + d0));
        for (int e = wid; e < TILE; e += 8) {
            const long long rr = rowi[e], cc = coli[e];
            float4 p = __ldg((const float4*)(g_P + rr * Hdim + d0));
            float4 q = __ldg((const float4*)(g_Q + cc * Hdim + d0));
            const float d2 = d2s[e];
            As[(d0 + 0) * LDA + e] = silu_f(fmaf(d2, w1c.x, p.x + q.x));
            As[(d0 + 1) * LDA + e] = silu_f(fmaf(d2, w1c.y, p.y + q.y));
            As[(d0 + 2) * LDA + e] = silu_f(fmaf(d2, w1c.z, p.z + q.z));
            As[(d0 + 3) * LDA + e] = silu_f(fmaf(d2, w1c.w, p.w + q.w));
        }
    }
    // (gemm_warpcol opens with __syncthreads)

    unsigned long long acc[2][8];

    // 3) m_ij = silu(m1 @ We2 + be2); scatter to m_i; stash into As
    gemm_warpcol(As, Ws, We2, be2, acc, tid, lane, c0);

    // Unpack per COLUMN pairs: acc[e][j] = (col c0+2j, col c0+2j+1) of edge e.
    float f0[16], f1[16];
#pragma unroll
    for (int j = 0; j < 8; j++) {
        float v0, v1;
        upk2(acc[0][j], v0, v1); f0[2 * j] = silu_f(v0); f0[2 * j + 1] = silu_f(v1);
        upk2(acc[1][j], v0, v1); f1[2 * j] = silu_f(v0); f1[2 * j + 1] = silu_f(v1);
    }
    {
        float* p0 = g_mi + (long long)rowi[e0] * Hdim + c0;
        float* p1 = g_mi + (long long)rowi[e1] * Hdim + c0;
        red_add_v4(p0,      f0[0],  f0[1],  f0[2],  f0[3]);
        red_add_v4(p0 + 4,  f0[4],  f0[5],  f0[6],  f0[7]);
        red_add_v4(p0 + 8,  f0[8],  f0[9],  f0[10], f0[11]);
        red_add_v4(p0 + 12, f0[12], f0[13], f0[14], f0[15]);
        red_add_v4(p1,      f1[0],  f1[1],  f1[2],  f1[3]);
        red_add_v4(p1 + 4,  f1[4],  f1[5],  f1[6],  f1[7]);
        red_add_v4(p1 + 8,  f1[8],  f1[9],  f1[10], f1[11]);
        red_add_v4(p1 + 12, f1[12], f1[13], f1[14], f1[15]);
    }
    __syncthreads();  // all warps done reading m1 from As
#pragma unroll
    for (int j = 0; j < 16; j++)
        *(unsigned long long*)(As + (c0 + j) * LDA + e0) = pk2(f0[j], f1[j]);
    // (gemm_warpcol opens with __syncthreads — makes stash visible)

    // 4) c1 = silu(m_ij @ Wc1 + bc1); s = tanh(c1 . Wc2) * 0.1; force scatter
    gemm_warpcol(As, Ws, Wc1, bc1, acc, tid, lane, c0);

    float4 wcA = __ldg((const float4*)(Wc2 + c0));
    float4 wcB = __ldg((const float4*)(Wc2 + c0 + 4));
    float4 wcC = __ldg((const float4*)(Wc2 + c0 + 8));
    float4 wcD = __ldg((const float4*)(Wc2 + c0 + 12));
    float wcv[16] = {wcA.x, wcA.y, wcA.z, wcA.w, wcB.x, wcB.y, wcB.z, wcB.w,
                     wcC.x, wcC.y, wcC.z, wcC.w, wcD.x, wcD.y, wcD.z, wcD.w};
    float p0 = 0.0f, p1 = 0.0f;
#pragma unroll
    for (int j = 0; j < 8; j++) {
        float v0, v1;
        upk2(acc[0][j], v0, v1);   // edge e0, cols (2j, 2j+1)
        p0 = fmaf(silu_f(v0), wcv[2 * j], p0);
        p0 = fmaf(silu_f(v1), wcv[2 * j + 1], p0);
        upk2(acc[1][j], v0, v1);   // edge e1, cols (2j, 2j+1)
        p1 = fmaf(silu_f(v0), wcv[2 * j], p1);
        p1 = fmaf(silu_f(v1), wcv[2 * j + 1], p1);
    }
    atomicAdd(&sf[e0], p0);
    atomicAdd(&sf[e1], p1);
    __syncthreads();

    if (tid < TILE) {
        const float s = tanhf(sf[tid]) * 0.1f;
        float* px = out_x + (long long)rowi[tid] * 3;
        atomicAdd(px + 0, nd[0 * TILE + tid] * s);
        atomicAdd(px + 1, nd[1 * TILE + tid] * s);
        atomicAdd(px + 2, nd[2 * TILE + tid] * s);
    }
}

// ---------- node kernel: node MLP + residual + LayerNorm (R1 design) ----------
__global__ void __launch_bounds__(256, 2) node_kernel(
    const float* __restrict__ h,
    const float* __restrict__ Wn1, const float* __restrict__ bn1,
    const float* __restrict__ Wn2, const float* __restrict__ bn2,
    const float* __restrict__ lng, const float* __restrict__ lnb,
    float* __restrict__ out_h) {
    extern __shared__ float sm[];
    float* As = sm;               // 256 * LDA
    float* Bs = As + 256 * LDA;   // 128 * LDA

    const int tid = threadIdx.x;
    const int tx = tid & 31, ty = tid >> 5;
    const int r0 = ty * 8;
    const int nb = blockIdx.x * TILE;

    for (int e = ty; e < TILE; e += 8) {
        const int node = nb + e;
        const int d0 = tx * 4;
        if (node < NNODES) {
            float4 hv = __ldg((const float4*)(h + (long long)node * Hdim + d0));
            As[(d0 + 0) * LDA + e] = hv.x;
            As[(d0 + 1) * LDA + e] = hv.y;
            As[(d0 + 2) * LDA + e] = hv.z;
            As[(d0 + 3) * LDA + e] = hv.w;
            float4 mv = *(const float4*)(g_mi + (long long)node * Hdim + d0);
            As[(Hdim + d0 + 0) * LDA + e] = mv.x;
            As[(Hdim + d0 + 1) * LDA + e] = mv.y;
            As[(Hdim + d0 + 2) * LDA + e] = mv.z;
            As[(Hdim + d0 + 3) * LDA + e] = mv.w;
        } else {
#pragma unroll
            for (int q = 0; q < 4; q++) {
                As[(d0 + q) * LDA + e] = 0.0f;
                As[(Hdim + d0 + q) * LDA + e] = 0.0f;
            }
        }
    }
    __syncthreads();

    unsigned long long acc[4][4];
    gemm_tile<256>(As, Wn1, bn1, acc, tx, r0);
#pragma unroll
    for (int i = 0; i < 4; i++) {
#pragma unroll
        for (int j = 0; j < 4; j++) {
            float v0, v1; upk2(acc[i][j], v0, v1);
            *(unsigned long long*)(Bs + (tx * 4 + j) * LDA + r0 + 2 * i) =
                pk2(silu_f(v0), silu_f(v1));
        }
    }
    __syncthreads();

    gemm_tile<128>(Bs, Wn2, bn2, acc, tx, r0);

    float v[8][4];
#pragma unroll
    for (int i = 0; i < 4; i++) {
        const int n0 = nb + r0 + 2 * i, n1 = n0 + 1;
        float4 hA = make_float4(0.f, 0.f, 0.f, 0.f);
        float4 hB = make_float4(0.f, 0.f, 0.f, 0.f);
        if (n0 < NNODES) hA = __ldg((const float4*)(h + (long long)n0 * Hdim + tx * 4));
        if (n1 < NNODES) hB = __ldg((const float4*)(h + (long long)n1 * Hdim + tx * 4));
        float v0, v1;
        upk2(acc[i][0], v0, v1); v[2 * i][0] = v0 + hA.x; v[2 * i + 1][0] = v1 + hB.x;
        upk2(acc[i][1], v0, v1); v[2 * i][1] = v0 + hA.y; v[2 * i + 1][1] = v1 + hB.y;
        upk2(acc[i][2], v0, v1); v[2 * i][2] = v0 + hA.z; v[2 * i + 1][2] = v1 + hB.z;
        upk2(acc[i][3], v0, v1); v[2 * i][3] = v0 + hA.w; v[2 * i + 1][3] = v1 + hB.w;
    }

    float4 g4 = __ldg((const float4*)(lng + tx * 4));
    float4 b4 = __ldg((const float4*)(lnb + tx * 4));
#pragma unroll
    for (int rr = 0; rr < 8; rr++) {
        float s = v[rr][0] + v[rr][1] + v[rr][2] + v[rr][3];
        float q = v[rr][0] * v[rr][0] + v[rr][1] * v[rr][1] +
                  v[rr][2] * v[rr][2] + v[rr][3] * v[rr][3];
#pragma unroll
        for (int off = 16; off > 0; off >>= 1) {
            s += __shfl_xor_sync(0xffffffffu, s, off);
            q += __shfl_xor_sync(0xffffffffu, q, off);
        }
        const float mu = s * (1.0f / 128.0f);
        const float var = q * (1.0f / 128.0f) - mu * mu;
        const float rstd = rsqrtf(var + 1e-5f);
        const int node = nb + r0 + rr;
        if (node < NNODES) {
            float4 o;
            o.x = (v[rr][0] - mu) * rstd * g4.x + b4.x;
            o.y = (v[rr][1] - mu) * rstd * g4.y + b4.y;
            o.z = (v[rr][2] - mu) * rstd * g4.z + b4.z;
            o.w = (v[rr][3] - mu) * rstd * g4.w + b4.w;
            *(float4*)(out_h + (long long)node * Hdim + tx * 4) = o;
        }
    }
}

// ---------- launch ----------
extern "C" void kernel_launch(void* const* d_in, const int* in_sizes, int n_in,
                              void* d_out, int out_size) {
    const float* h   = (const float*)d_in[0];
    const float* x   = (const float*)d_in[1];
    const void*  ei  = d_in[2];
    const float* We1 = (const float*)d_in[3];
    const float* be1 = (const float*)d_in[4];
    const float* We2 = (const float*)d_in[5];
    const float* be2 = (const float*)d_in[6];
    const float* Wc1 = (const float*)d_in[7];
    const float* bc1 = (const float*)d_in[8];
    const float* Wc2 = (const float*)d_in[9];
    const float* Wn1 = (const float*)d_in[10];
    const float* bn1 = (const float*)d_in[11];
    const float* Wn2 = (const float*)d_in[12];
    const float* bn2 = (const float*)d_in[13];
    const float* lng = (const float*)d_in[14];
    const float* lnb = (const float*)d_in[15];

    float* out_h = (float*)d_out;
    float* out_x = out_h + (long long)NNODES * Hdim;

    const int SMEM_PREP = (128 * LDA) * 4;
    const int SMEM_EDGE = (128 * LDA + KCHUNK * Hdim + 3 * TILE + TILE + TILE + 2 * TILE) * 4;
    const int SMEM_NODE = (256 * LDA + 128 * LDA) * 4;

    cudaFuncSetAttribute(prep_kernel, cudaFuncAttributeMaxDynamicSharedMemorySize, SMEM_PREP);
    cudaFuncSetAttribute(edge_kernel, cudaFuncAttributeMaxDynamicSharedMemorySize, SMEM_EDGE);
    cudaFuncSetAttribute(node_kernel, cudaFuncAttributeMaxDynamicSharedMemorySize, SMEM_NODE);

    detect_kernel<<<1, 32>>>((const int*)ei);
    init_kernel<<<((long long)NNODES * Hdim + 255) / 256, 256>>>(x, out_x);
    prep_kernel<<<(NNODES + TILE - 1) / TILE, 256, SMEM_PREP>>>(h, We1, be1);
    edge_kernel<<<NEDGES / TILE, 256, SMEM_EDGE>>>(x, ei, We1, We2, be2,
                                                   Wc1, bc1, Wc2, out_x);
    node_kernel<<<(NNODES + TILE - 1) / TILE, 256, SMEM_NODE>>>(h, Wn1, bn1, Wn2, bn2,
                                                                lng, lnb, out_h);
}

// round 6
// speedup vs baseline: 1.0846x; 1.0846x over previous
#include <cuda_runtime.h>

#define Hdim 128
#define NNODES 50000
#define NEDGES 800000
#define TILE 64
#define LDA 68   // padded feature-major stride; mult of 4 => 16B-aligned row quads

__device__ int   g_is64;
__device__ float g_mi[(long long)NNODES * Hdim];  // segment-summed m_i scratch
__device__ float g_P [(long long)NNODES * Hdim];  // h @ We1[0:128]   + be1
__device__ float g_Q [(long long)NNODES * Hdim];  // h @ We1[128:256]

// ---------- f32x2 helpers ----------
__device__ __forceinline__ unsigned long long pk2(float lo, float hi) {
    unsigned long long r;
    asm("mov.b64 %0, {%1,%2};" : "=l"(r) : "f"(lo), "f"(hi));
    return r;
}
__device__ __forceinline__ void upk2(unsigned long long v, float& lo, float& hi) {
    asm("mov.b64 {%0,%1}, %2;" : "=f"(lo), "=f"(hi) : "l"(v));
}
#define FMA2(d, a, b) asm("fma.rn.f32x2 %0, %1, %2, %0;" : "+l"(d) : "l"(a), "l"(b))

__device__ __forceinline__ void red_add_v4(float* p, float a, float b, float c, float d) {
    asm volatile("red.global.add.v4.f32 [%0], {%1,%2,%3,%4};"
                 :: "l"(p), "f"(a), "f"(b), "f"(c), "f"(d) : "memory");
}

__device__ __forceinline__ float silu_f(float v) { return v / (1.0f + __expf(-v)); }

// ---------- GEMM tile: C[64 rows x 128 cols] = A[64 x K] * W[K x 128] (+ bias) ----------
// A feature-major in smem: A[k*LDA + row]. Thread (tx,ty): rows r0..r0+7 as 4 packed
// pairs (loaded as 2 x LDS.128 broadcast), cols tx*4..tx*4+3 (1 x LDG.128, L1-hit).
// Per warp-k: 2 LDS.128 + 1 LDG.128 + 16 FFMA2  => FMA-pipe-bound.
template <int K>
__device__ __forceinline__ void gemm_tile(const float* __restrict__ As,
                                          const float* __restrict__ W,
                                          const float* __restrict__ bias,
                                          unsigned long long acc[4][4],
                                          int tx, int r0) {
    float4 b4 = bias ? __ldg((const float4*)(bias + tx * 4))
                     : make_float4(0.f, 0.f, 0.f, 0.f);
#pragma unroll
    for (int i = 0; i < 4; i++) {
        acc[i][0] = pk2(b4.x, b4.x);
        acc[i][1] = pk2(b4.y, b4.y);
        acc[i][2] = pk2(b4.z, b4.z);
        acc[i][3] = pk2(b4.w, b4.w);
    }
#pragma unroll 4
    for (int k = 0; k < K; k++) {
        float4 w = __ldg((const float4*)(W + (long long)k * Hdim + tx * 4));
        unsigned long long w0 = pk2(w.x, w.x);
        unsigned long long w1 = pk2(w.y, w.y);
        unsigned long long w2 = pk2(w.z, w.z);
        unsigned long long w3 = pk2(w.w, w.w);
        const float* ak = As + k * LDA + r0;
        ulonglong2 aP = *(const ulonglong2*)(ak);      // row pairs (r0,r0+1),(r0+2,r0+3)
        ulonglong2 aQ = *(const ulonglong2*)(ak + 4);  // row pairs (r0+4,..),(r0+6,..)
        unsigned long long a2[4] = {aP.x, aP.y, aQ.x, aQ.y};
#pragma unroll
        for (int i = 0; i < 4; i++) {
            FMA2(acc[i][0], a2[i], w0);
            FMA2(acc[i][1], a2[i], w1);
            FMA2(acc[i][2], a2[i], w2);
            FMA2(acc[i][3], a2[i], w3);
        }
    }
}

// ---------- index dtype detection (int32 vs int64) ----------
__global__ void detect_kernel(const int* ei32) {
    if (blockIdx.x == 0 && threadIdx.x == 0) {
        int f = 1;
        for (int i = 0; i < 1024; i++) {
            if (ei32[2 * i + 1] != 0) { f = 0; break; }
        }
        g_is64 = f;
    }
}

// ---------- init: zero m_i scratch, seed out_x = x ----------
__global__ void init_kernel(const float* __restrict__ x, float* __restrict__ out_x) {
    long long i = (long long)blockIdx.x * blockDim.x + threadIdx.x;
    if (i < (long long)NNODES * Hdim) g_mi[i] = 0.0f;
    if (i < (long long)NNODES * 3)    out_x[i] = x[i];
}

// ---------- prep: P = h @ We1[0:128] + be1 ; Q = h @ We1[128:256] ----------
__global__ void __launch_bounds__(256) prep_kernel(
    const float* __restrict__ h,
    const float* __restrict__ We1, const float* __restrict__ be1) {
    extern __shared__ float sm[];
    float* As = sm;  // 128 * LDA

    const int tid = threadIdx.x;
    const int tx = tid & 31, ty = tid >> 5;
    const int r0 = ty * 8;
    const int nb = blockIdx.x * TILE;

    for (int e = ty; e < TILE; e += 8) {
        const int node = nb + e;
        const int d0 = tx * 4;
        float4 hv = make_float4(0.f, 0.f, 0.f, 0.f);
        if (node < NNODES) hv = __ldg((const float4*)(h + (long long)node * Hdim + d0));
        As[(d0 + 0) * LDA + e] = hv.x;
        As[(d0 + 1) * LDA + e] = hv.y;
        As[(d0 + 2) * LDA + e] = hv.z;
        As[(d0 + 3) * LDA + e] = hv.w;
    }
    __syncthreads();

    unsigned long long acc[4][4];

    gemm_tile<128>(As, We1, be1, acc, tx, r0);
#pragma unroll
    for (int i = 0; i < 4; i++) {
        const int n0 = nb + r0 + 2 * i, n1 = n0 + 1;
        float4 oA, oB;
        float v0, v1;
        upk2(acc[i][0], v0, v1); oA.x = v0; oB.x = v1;
        upk2(acc[i][1], v0, v1); oA.y = v0; oB.y = v1;
        upk2(acc[i][2], v0, v1); oA.z = v0; oB.z = v1;
        upk2(acc[i][3], v0, v1); oA.w = v0; oB.w = v1;
        if (n0 < NNODES) *(float4*)(g_P + (long long)n0 * Hdim + tx * 4) = oA;
        if (n1 < NNODES) *(float4*)(g_P + (long long)n1 * Hdim + tx * 4) = oB;
    }

    gemm_tile<128>(As, We1 + 128 * Hdim, (const float*)0, acc, tx, r0);
#pragma unroll
    for (int i = 0; i < 4; i++) {
        const int n0 = nb + r0 + 2 * i, n1 = n0 + 1;
        float4 oA, oB;
        float v0, v1;
        upk2(acc[i][0], v0, v1); oA.x = v0; oB.x = v1;
        upk2(acc[i][1], v0, v1); oA.y = v0; oB.y = v1;
        upk2(acc[i][2], v0, v1); oA.z = v0; oB.z = v1;
        upk2(acc[i][3], v0, v1); oA.w = v0; oB.w = v1;
        if (n0 < NNODES) *(float4*)(g_Q + (long long)n0 * Hdim + tx * 4) = oA;
        if (n1 < NNODES) *(float4*)(g_Q + (long long)n1 * Hdim + tx * 4) = oB;
    }
}

// ---------- edge kernel: m1 via gather-add, then 2 fused GEMM layers ----------
__global__ void __launch_bounds__(256, 3) edge_kernel(
    const float* __restrict__ x, const void* __restrict__ ei,
    const float* __restrict__ We1,
    const float* __restrict__ We2, const float* __restrict__ be2,
    const float* __restrict__ Wc1, const float* __restrict__ bc1,
    const float* __restrict__ Wc2,
    float* __restrict__ out_x) {
    extern __shared__ float sm[];
    float* As = sm;                      // 128 * LDA (m1)
    float* Bs = As + 128 * LDA;          // 128 * LDA (m_ij)
    float* nd = Bs + 128 * LDA;          // 3 * TILE (normalized coord diffs)
    float* d2s = nd + 3 * TILE;          // TILE (radial)
    int*  rowi = (int*)(d2s + TILE);     // TILE
    int*  coli = rowi + TILE;            // TILE

    const int tid = threadIdx.x;
    const int tx = tid & 31, ty = tid >> 5;
    const int r0 = ty * 8;
    const int eb = blockIdx.x * TILE;
    const int is64 = g_is64;

    // 1) indices + coord geometry
    if (tid < TILE) {
        int e = tid;
        long long r, c;
        if (is64) {
            const long long* p = (const long long*)ei;
            r = p[eb + e]; c = p[NEDGES + eb + e];
        } else {
            const int* p = (const int*)ei;
            r = p[eb + e]; c = p[NEDGES + eb + e];
        }
        rowi[e] = (int)r; coli[e] = (int)c;
        float dx = __ldg(x + r * 3 + 0) - __ldg(x + c * 3 + 0);
        float dy = __ldg(x + r * 3 + 1) - __ldg(x + c * 3 + 1);
        float dz = __ldg(x + r * 3 + 2) - __ldg(x + c * 3 + 2);
        float d2 = dx * dx + dy * dy + dz * dz;
        float dist = sqrtf(d2);
        d2s[e] = d2;
        float inv = 1.0f / (dist + 1e-8f);
        nd[0 * TILE + e] = dx * inv;
        nd[1 * TILE + e] = dy * inv;
        nd[2 * TILE + e] = dz * inv;
    }
    __syncthreads();

    // 2) m1 = silu(P[row] + Q[col] + d2 * We1[256]) — layer-1 GEMM eliminated
    {
        const int d0 = tx * 4;
        float4 w1c = __ldg((const float4*)(We1 + 256 * Hdim + d0));
        for (int e = ty; e < TILE; e += 8) {
            const long long rr = rowi[e], cc = coli[e];
            float4 p = __ldg((const float4*)(g_P + rr * Hdim + d0));
            float4 q = __ldg((const float4*)(g_Q + cc * Hdim + d0));
            const float d2 = d2s[e];
            As[(d0 + 0) * LDA + e] = silu_f(fmaf(d2, w1c.x, p.x + q.x));
            As[(d0 + 1) * LDA + e] = silu_f(fmaf(d2, w1c.y, p.y + q.y));
            As[(d0 + 2) * LDA + e] = silu_f(fmaf(d2, w1c.z, p.z + q.z));
            As[(d0 + 3) * LDA + e] = silu_f(fmaf(d2, w1c.w, p.w + q.w));
        }
    }
    __syncthreads();

    unsigned long long acc[4][4];

    // 3) m_ij = silu(m1 @ We2 + be2); scatter to m_i and keep in Bs
    gemm_tile<128>(As, We2, be2, acc, tx, r0);
#pragma unroll
    for (int i = 0; i < 4; i++) {
        float m0[4], m1v[4];
#pragma unroll
        for (int j = 0; j < 4; j++) {
            float v0, v1; upk2(acc[i][j], v0, v1);
            m0[j] = silu_f(v0); m1v[j] = silu_f(v1);
            *(unsigned long long*)(Bs + (tx * 4 + j) * LDA + r0 + 2 * i) = pk2(m0[j], m1v[j]);
        }
        const int e0 = r0 + 2 * i, e1 = e0 + 1;
        red_add_v4(g_mi + (long long)rowi[e0] * Hdim + tx * 4, m0[0], m0[1], m0[2], m0[3]);
        red_add_v4(g_mi + (long long)rowi[e1] * Hdim + tx * 4, m1v[0], m1v[1], m1v[2], m1v[3]);
    }
    __syncthreads();

    // 4) c1 = silu(m_ij @ Wc1 + bc1); s = tanh(c1 . Wc2) * 0.1; force scatter
    gemm_tile<128>(Bs, Wc1, bc1, acc, tx, r0);
    float4 wc = __ldg((const float4*)(Wc2 + tx * 4));
    float par[8];
#pragma unroll
    for (int i = 0; i < 4; i++) {
        float p0 = 0.0f, p1 = 0.0f;
        {
            float v0, v1; upk2(acc[i][0], v0, v1);
            p0 += silu_f(v0) * wc.x; p1 += silu_f(v1) * wc.x;
        }
        {
            float v0, v1; upk2(acc[i][1], v0, v1);
            p0 += silu_f(v0) * wc.y; p1 += silu_f(v1) * wc.y;
        }
        {
            float v0, v1; upk2(acc[i][2], v0, v1);
            p0 += silu_f(v0) * wc.z; p1 += silu_f(v1) * wc.z;
        }
        {
            float v0, v1; upk2(acc[i][3], v0, v1);
            p0 += silu_f(v0) * wc.w; p1 += silu_f(v1) * wc.w;
        }
        par[2 * i] = p0; par[2 * i + 1] = p1;
    }
#pragma unroll
    for (int i = 0; i < 8; i++) {
#pragma unroll
        for (int off = 16; off > 0; off >>= 1)
            par[i] += __shfl_xor_sync(0xffffffffu, par[i], off);
    }
    if (tx == 0) {
#pragma unroll
        for (int i = 0; i < 8; i++) {
            const int e = r0 + i;
            const float s = tanhf(par[i]) * 0.1f;
            float* px = out_x + (long long)rowi[e] * 3;
            atomicAdd(px + 0, nd[0 * TILE + e] * s);
            atomicAdd(px + 1, nd[1 * TILE + e] * s);
            atomicAdd(px + 2, nd[2 * TILE + e] * s);
        }
    }
}

// ---------- node kernel: node MLP + residual + LayerNorm ----------
__global__ void __launch_bounds__(256, 2) node_kernel(
    const float* __restrict__ h,
    const float* __restrict__ Wn1, const float* __restrict__ bn1,
    const float* __restrict__ Wn2, const float* __restrict__ bn2,
    const float* __restrict__ lng, const float* __restrict__ lnb,
    float* __restrict__ out_h) {
    extern __shared__ float sm[];
    float* As = sm;               // 256 * LDA
    float* Bs = As + 256 * LDA;   // 128 * LDA

    const int tid = threadIdx.x;
    const int tx = tid & 31, ty = tid >> 5;
    const int r0 = ty * 8;
    const int nb = blockIdx.x * TILE;

    for (int e = ty; e < TILE; e += 8) {
        const int node = nb + e;
        const int d0 = tx * 4;
        if (node < NNODES) {
            float4 hv = __ldg((const float4*)(h + (long long)node * Hdim + d0));
            As[(d0 + 0) * LDA + e] = hv.x;
            As[(d0 + 1) * LDA + e] = hv.y;
            As[(d0 + 2) * LDA + e] = hv.z;
            As[(d0 + 3) * LDA + e] = hv.w;
            float4 mv = *(const float4*)(g_mi + (long long)node * Hdim + d0);
            As[(Hdim + d0 + 0) * LDA + e] = mv.x;
            As[(Hdim + d0 + 1) * LDA + e] = mv.y;
            As[(Hdim + d0 + 2) * LDA + e] = mv.z;
            As[(Hdim + d0 + 3) * LDA + e] = mv.w;
        } else {
#pragma unroll
            for (int q = 0; q < 4; q++) {
                As[(d0 + q) * LDA + e] = 0.0f;
                As[(Hdim + d0 + q) * LDA + e] = 0.0f;
            }
        }
    }
    __syncthreads();

    unsigned long long acc[4][4];
    gemm_tile<256>(As, Wn1, bn1, acc, tx, r0);
#pragma unroll
    for (int i = 0; i < 4; i++) {
#pragma unroll
        for (int j = 0; j < 4; j++) {
            float v0, v1; upk2(acc[i][j], v0, v1);
            *(unsigned long long*)(Bs + (tx * 4 + j) * LDA + r0 + 2 * i) =
                pk2(silu_f(v0), silu_f(v1));
        }
    }
    __syncthreads();

    gemm_tile<128>(Bs, Wn2, bn2, acc, tx, r0);

    float v[8][4];
#pragma unroll
    for (int i = 0; i < 4; i++) {
        const int n0 = nb + r0 + 2 * i, n1 = n0 + 1;
        float4 hA = make_float4(0.f, 0.f, 0.f, 0.f);
        float4 hB = make_float4(0.f, 0.f, 0.f, 0.f);
        if (n0 < NNODES) hA = __ldg((const float4*)(h + (long long)n0 * Hdim + tx * 4));
        if (n1 < NNODES) hB = __ldg((const float4*)(h + (long long)n1 * Hdim + tx * 4));
        float v0, v1;
        upk2(acc[i][0], v0, v1); v[2 * i][0] = v0 + hA.x; v[2 * i + 1][0] = v1 + hB.x;
        upk2(acc[i][1], v0, v1); v[2 * i][1] = v0 + hA.y; v[2 * i + 1][1] = v1 + hB.y;
        upk2(acc[i][2], v0, v1); v[2 * i][2] = v0 + hA.z; v[2 * i + 1][2] = v1 + hB.z;
        upk2(acc[i][3], v0, v1); v[2 * i][3] = v0 + hA.w; v[2 * i + 1][3] = v1 + hB.w;
    }

    float4 g4 = __ldg((const float4*)(lng + tx * 4));
    float4 b4 = __ldg((const float4*)(lnb + tx * 4));
#pragma unroll
    for (int rr = 0; rr < 8; rr++) {
        float s = v[rr][0] + v[rr][1] + v[rr][2] + v[rr][3];
        float q = v[rr][0] * v[rr][0] + v[rr][1] * v[rr][1] +
                  v[rr][2] * v[rr][2] + v[rr][3] * v[rr][3];
#pragma unroll
        for (int off = 16; off > 0; off >>= 1) {
            s += __shfl_xor_sync(0xffffffffu, s, off);
            q += __shfl_xor_sync(0xffffffffu, q, off);
        }
        const float mu = s * (1.0f / 128.0f);
        const float var = q * (1.0f / 128.0f) - mu * mu;
        const float rstd = rsqrtf(var + 1e-5f);
        const int node = nb + r0 + rr;
        if (node < NNODES) {
            float4 o;
            o.x = (v[rr][0] - mu) * rstd * g4.x + b4.x;
            o.y = (v[rr][1] - mu) * rstd * g4.y + b4.y;
            o.z = (v[rr][2] - mu) * rstd * g4.z + b4.z;
            o.w = (v[rr][3] - mu) * rstd * g4.w + b4.w;
            *(float4*)(out_h + (long long)node * Hdim + tx * 4) = o;
        }
    }
}

// ---------- launch ----------
extern "C" void kernel_launch(void* const* d_in, const int* in_sizes, int n_in,
                              void* d_out, int out_size) {
    const float* h   = (const float*)d_in[0];
    const float* x   = (const float*)d_in[1];
    const void*  ei  = d_in[2];
    const float* We1 = (const float*)d_in[3];
    const float* be1 = (const float*)d_in[4];
    const float* We2 = (const float*)d_in[5];
    const float* be2 = (const float*)d_in[6];
    const float* Wc1 = (const float*)d_in[7];
    const float* bc1 = (const float*)d_in[8];
    const float* Wc2 = (const float*)d_in[9];
    const float* Wn1 = (const float*)d_in[10];
    const float* bn1 = (const float*)d_in[11];
    const float* Wn2 = (const float*)d_in[12];
    const float* bn2 = (const float*)d_in[13];
    const float* lng = (const float*)d_in[14];
    const float* lnb = (const float*)d_in[15];

    float* out_h = (float*)d_out;
    float* out_x = out_h + (long long)NNODES * Hdim;

    const int SMEM_PREP = (128 * LDA) * 4;
    const int SMEM_EDGE = (128 * LDA * 2 + 3 * TILE + TILE + 2 * TILE) * 4;
    const int SMEM_NODE = (256 * LDA + 128 * LDA) * 4;

    cudaFuncSetAttribute(prep_kernel, cudaFuncAttributeMaxDynamicSharedMemorySize, SMEM_PREP);
    cudaFuncSetAttribute(edge_kernel, cudaFuncAttributeMaxDynamicSharedMemorySize, SMEM_EDGE);
    cudaFuncSetAttribute(node_kernel, cudaFuncAttributeMaxDynamicSharedMemorySize, SMEM_NODE);

    detect_kernel<<<1, 32>>>((const int*)ei);
    init_kernel<<<((long long)NNODES * Hdim + 255) / 256, 256>>>(x, out_x);
    prep_kernel<<<(NNODES + TILE - 1) / TILE, 256, SMEM_PREP>>>(h, We1, be1);
    edge_kernel<<<NEDGES / TILE, 256, SMEM_EDGE>>>(x, ei, We1, We2, be2,
                                                   Wc1, bc1, Wc2, out_x);
    node_kernel<<<(NNODES + TILE - 1) / TILE, 256, SMEM_NODE>>>(h, Wn1, bn1, Wn2, bn2,
                                                                lng, lnb, out_h);
}